// round 7
// baseline (speedup 1.0000x reference)
#include <cuda_runtime.h>

#define Tlen  8192
#define Bsz   4
#define RES   256
#define SKIPC 512
#define NCLSC 256
#define NLAY  30
#define WIN   3072
#define HSTR  3200
#define KT    16
#define ASROW 640     // dup-padded row: 4 quarters x 8 groups x 20 floats

typedef unsigned long long ull;

// ---------------- device scratch (allocation-free) ----------------
__device__ float g_h[2][Bsz][RES][HSTR];          // ping-pong hidden state; pads zero
__device__ float g_WdT2[NLAY * 512 * ASROW];      // dup+skewed transposed conv weights
__device__ float g_WrT2[NLAY * 256 * ASROW];      // dup+skewed transposed residual weights
__device__ float g_gLast[NLAY][Bsz][RES];
__device__ float g_skip[Bsz][SKIPC];

// ---------------- helpers ----------------
__device__ __forceinline__ ull fma2(ull a, ull b, ull c) {
    ull d; asm("fma.rn.f32x2 %0, %1, %2, %3;" : "=l"(d) : "l"(a), "l"(b), "l"(c)); return d;
}
__device__ __forceinline__ float2 upk(ull v) {
    float2 f; asm("mov.b64 {%0,%1}, %2;" : "=f"(f.x), "=f"(f.y) : "l"(v)); return f;
}
__device__ __forceinline__ float gate_fn(float d) {
    float e1 = __expf(-d);
    float sg = __fdividef(1.f, 1.f + e1);
    float th = __fdividef(2.f, 1.f + e1 * e1) - 1.f;
    return th * sg;
}
__device__ __forceinline__ unsigned su32(const void* p) {
    return (unsigned)__cvta_generic_to_shared(p);
}

#define CPA16(d, s) asm volatile("cp.async.cg.shared.global [%0],[%1],16;\n" :: "r"(d), "l"(s))
#define CPA4(d, s)  asm volatile("cp.async.ca.shared.global [%0],[%1],4;\n"  :: "r"(d), "l"(s))
#define CPCOMMIT()  asm volatile("cp.async.commit_group;\n")
#define CPWAIT0()   asm volatile("cp.async.wait_group 0;\n" ::: "memory")

// ---------------- prep: transpose + duplicate + bank-skew weights ----------------
// dst[(lay*K + k)*ASROW + q*160 + cl*20 + 2*j {,+1}] = W[(lay*256 + co)*K + k],
// where co = q*64 + cl*8 + j.
__global__ void prep_dup(const float* __restrict__ W, float* __restrict__ dst, int K) {
    int k   = blockIdx.x;
    int lay = blockIdx.y;
    int co  = threadIdx.x;
    float v = W[((size_t)lay * 256 + co) * K + k];
    int q = co >> 6, cl = (co >> 3) & 7, j = co & 7;
    float* d = dst + ((size_t)lay * K + k) * ASROW + q * 160 + cl * 20 + 2 * j;
    d[0] = v; d[1] = v;
}

// ---------------- start conv ----------------
__global__ void start_conv(const float* __restrict__ x,
                           const float* __restrict__ Wst,
                           const float* __restrict__ bst) {
    int b = blockIdx.y;
    int u = blockIdx.x * 256 + threadIdx.x;
    int t = (Tlen - WIN) + u;
    float x0 = x[b * Tlen + t - 1];
    float x1 = x[b * Tlen + t];
    for (int c = 0; c < RES; c++)
        g_h[0][b][c][u] = bst[c] + Wst[2 * c] * x0 + Wst[2 * c + 1] * x1;
}

// ---------------- fused layer kernel ----------------
// Warp tile: 64 channels (cw quarter) x 4*NT columns (uw group).
// lane: cl = lane>>2 (8 channel-groups of 8), ul = lane&3 (4 column-subgroups of NT).
// A: dup pairs via 4x LDS.128, skewed -> 1 wf each. B: contiguous col pairs -> 1 wf.
template <int NT, int NUW>
__global__ void __launch_bounds__(128 * NUW, 1)
layer_kernel(int pp,
             const float* __restrict__ WA,  const float* __restrict__ bd,
             const float* __restrict__ WA2, const float* __restrict__ br,
             int dil, int u0, int layer) {
    constexpr int BN  = 4 * NT * NUW;
    constexpr int TPB = 128 * NUW;
    constexpr int NP  = NT / 2;

    extern __shared__ float smem[];
    float* As0 = smem;                                    // 2 x [KT][ASROW]
    float* Bs0 = smem + 2 * KT * ASROW;                   // 2 x [KT][BN]
    float* gs  = smem + 2 * KT * ASROW + 2 * KT * BN;     // [RES][BN]

    const int tid  = threadIdx.x;
    const int lane = tid & 31;
    const int w    = tid >> 5;
    const int cw   = w & 3;
    const int uw   = w >> 2;
    const int cl   = lane >> 2;
    const int ul   = lane & 3;
    const int chb  = cw * 64 + cl * 8;          // 8 channels chb..chb+7
    const int colb = uw * 4 * NT + ul * NT;     // NT columns colb..colb+NT-1
    const int b    = blockIdx.y;
    const int ub   = u0 + blockIdx.x * BN;

    const float* hin  = &g_h[pp][b][0][0];
    float*       hout = &g_h[pp ^ 1][b][0][0];

    ull acc[8][NP];
#pragma unroll
    for (int p = 0; p < 8; p++)
#pragma unroll
        for (int q = 0; q < NP; q++) acc[p][q] = 0ull;

    auto stageA = [&](int s, const float* src) {          // KT x ASROW contiguous
        float* dstb = As0 + s * KT * ASROW;
        for (int i = tid; i < KT * (ASROW / 4); i += TPB)
            CPA16(su32(dstb + 4 * i), src + 4 * i);
    };
    auto stageB = [&](int s, int k0) {
        float* dstb = Bs0 + s * KT * BN;
#pragma unroll
        for (int e = tid; e < KT * BN; e += TPB) {
            int kr = e / BN, u = e - kr * BN;
            int r  = k0 + kr;
            int ci = r >> 1;
            int off = (r & 1) ? 0 : dil;
            CPA4(su32(dstb + e), hin + ci * HSTR + (ub + u - off));
        }
    };

    auto compute = [&](const float* A, const float* B) {
#pragma unroll
        for (int kk = 0; kk < KT; kk++) {
            const float* ar = A + kk * ASROW + cw * 160 + cl * 20;
            ulonglong2 t0 = *(const ulonglong2*)(ar);
            ulonglong2 t1 = *(const ulonglong2*)(ar + 4);
            ulonglong2 t2 = *(const ulonglong2*)(ar + 8);
            ulonglong2 t3 = *(const ulonglong2*)(ar + 12);
            ull a2[8] = {t0.x, t0.y, t1.x, t1.y, t2.x, t2.y, t3.x, t3.y};
            ull b2[NP];
            const float* bp = B + kk * BN + colb;
            if (NT == 8) {
                ulonglong2 u0v = *(const ulonglong2*)(bp);
                ulonglong2 u1v = *(const ulonglong2*)(bp + 4);
                b2[0] = u0v.x; b2[1] = u0v.y; b2[2] = u1v.x; b2[3] = u1v.y;
            } else if (NT == 4) {
                ulonglong2 u0v = *(const ulonglong2*)(bp);
                b2[0] = u0v.x; b2[1] = u0v.y;
            } else {
                b2[0] = *(const ull*)(bp);
            }
#pragma unroll
            for (int p = 0; p < 8; p++)
#pragma unroll
                for (int q = 0; q < NP; q++) acc[p][q] = fma2(a2[p], b2[q], acc[p][q]);
        }
    };

    // ---- phase 1: dilated conv, K = 512 (32 tiles of KT=16) ----
    stageA(0, WA); stageB(0, 0); CPCOMMIT();
    int cur = 0;
    for (int t = 0; t < 32; t++) {
        CPWAIT0(); __syncthreads();
        if (t + 1 < 32) { stageA(cur ^ 1, WA + (size_t)(t + 1) * KT * ASROW); stageB(cur ^ 1, (t + 1) * KT); }
        else            { stageA(cur ^ 1, WA2); }   // prefetch phase-2 tile 0
        CPCOMMIT();
        compute(As0 + cur * KT * ASROW, Bs0 + cur * KT * BN);
        cur ^= 1;
    }

    // ---- gate -> gs, extract t = T-1 column, reset acc ----
#pragma unroll
    for (int p = 0; p < 8; p++) {
        int co = chb + p;
        float bdv = bd[co];
#pragma unroll
        for (int q = 0; q < NP; q++) {
            float2 v = upk(acc[p][q]);
            float g0 = gate_fn(v.x + bdv);
            float g1 = gate_fn(v.y + bdv);
            int col = colb + 2 * q;
            gs[co * BN + col]     = g0;
            gs[co * BN + col + 1] = g1;
            int uu = ub + col;
            if (uu == WIN - 1)     g_gLast[layer][b][co] = g0;
            if (uu + 1 == WIN - 1) g_gLast[layer][b][co] = g1;
            acc[p][q] = 0ull;
        }
    }

    // ---- phase 2: residual GEMM, K = 256 (16 tiles), B = gs ----
    for (int t = 0; t < 16; t++) {
        CPWAIT0(); __syncthreads();    // publishes gs before first read
        if (t + 1 < 16) stageA(cur ^ 1, WA2 + (size_t)(t + 1) * KT * ASROW);
        CPCOMMIT();
        compute(As0 + cur * KT * ASROW, gs + t * KT * BN);
        cur ^= 1;
    }

    // ---- residual epilogue ----
#pragma unroll
    for (int p = 0; p < 8; p++) {
        int co = chb + p;
        float brv = br[co];
#pragma unroll
        for (int q = 0; q < NP; q++) {
            float2 v = upk(acc[p][q]);
            int uu = ub + colb + 2 * q;
            if (uu < WIN)     hout[co * HSTR + uu]     = hin[co * HSTR + uu]     + v.x + brv;
            if (uu + 1 < WIN) hout[co * HSTR + uu + 1] = hin[co * HSTR + uu + 1] + v.y + brv;
        }
    }
}

// ---------------- skip head ----------------
__global__ void skip_kernel(const float* __restrict__ Ws, const float* __restrict__ bs) {
    int b = blockIdx.x;
    int w = threadIdx.x >> 5;
    int lane = threadIdx.x & 31;
    int so_base = blockIdx.y * 64 + w * 8;
    for (int oi = 0; oi < 8; oi++) {
        int so = so_base + oi;
        float v = (lane < NLAY) ? bs[lane * SKIPC + so] : 0.f;
        for (int l = 0; l < NLAY; l++) {
            const float* wr = Ws + ((size_t)l * SKIPC + so) * RES;
            const float* gg = &g_gLast[l][b][0];
#pragma unroll
            for (int k = lane; k < RES; k += 32) v += wr[k] * gg[k];
        }
#pragma unroll
        for (int s = 16; s; s >>= 1) v += __shfl_xor_sync(0xffffffffu, v, s);
        if (lane == 0) g_skip[b][so] = fmaxf(v, 0.f);
    }
}

// ---------------- end head ----------------
__global__ void end_kernel(const float* __restrict__ We1, const float* __restrict__ be1,
                           const float* __restrict__ We2, const float* __restrict__ be2,
                           float* __restrict__ out) {
    __shared__ float sk[SKIPC];
    __shared__ float mid[SKIPC];
    int b = blockIdx.x;
    int tid = threadIdx.x;
    int w = tid >> 5, lane = tid & 31;
    for (int i = tid; i < SKIPC; i += 256) sk[i] = g_skip[b][i];
    __syncthreads();
    for (int oi = 0; oi < 64; oi++) {
        int so = w * 64 + oi;
        const float* row = We1 + (size_t)so * SKIPC;
        float v = 0.f;
#pragma unroll
        for (int k = lane; k < SKIPC; k += 32) v += row[k] * sk[k];
#pragma unroll
        for (int s = 16; s; s >>= 1) v += __shfl_xor_sync(0xffffffffu, v, s);
        if (lane == 0) mid[so] = fmaxf(v + be1[so], 0.f);
    }
    __syncthreads();
    for (int oi = 0; oi < 32; oi++) {
        int nc = w * 32 + oi;
        const float* row = We2 + (size_t)nc * SKIPC;
        float v = 0.f;
#pragma unroll
        for (int k = lane; k < SKIPC; k += 32) v += row[k] * mid[k];
#pragma unroll
        for (int s = 16; s; s >>= 1) v += __shfl_xor_sync(0xffffffffu, v, s);
        if (lane == 0) out[b * NCLSC + nc] = v + be2[nc];
    }
}

// ---------------- host ----------------
static const int DILS[NLAY] = {1,2,4,8,16,32,64,128,256,512,
                               1,2,4,8,16,32,64,128,256,512,
                               1,2,4,8,16,32,64,128,256,512};

static inline size_t smem_for(int BN) {
    return (size_t)(2 * KT * ASROW + 2 * KT * BN + RES * BN) * sizeof(float);
}

extern "C" void kernel_launch(void* const* d_in, const int* in_sizes, int n_in,
                              void* d_out, int out_size) {
    (void)in_sizes; (void)n_in; (void)out_size;
    const float* x   = (const float*)d_in[0];
    const float* Wst = (const float*)d_in[1];
    const float* bst = (const float*)d_in[2];
    const float* Wd  = (const float*)d_in[3];
    const float* bd  = (const float*)d_in[4];
    const float* Wr  = (const float*)d_in[5];
    const float* br  = (const float*)d_in[6];
    const float* Ws  = (const float*)d_in[7];
    const float* bs  = (const float*)d_in[8];
    const float* We1 = (const float*)d_in[9];
    const float* be1 = (const float*)d_in[10];
    const float* We2 = (const float*)d_in[11];
    const float* be2 = (const float*)d_in[12];
    float* out = (float*)d_out;

    cudaFuncSetAttribute((const void*)layer_kernel<8, 3>, cudaFuncAttributeMaxDynamicSharedMemorySize, (int)smem_for(96));
    cudaFuncSetAttribute((const void*)layer_kernel<4, 4>, cudaFuncAttributeMaxDynamicSharedMemorySize, (int)smem_for(64));
    cudaFuncSetAttribute((const void*)layer_kernel<2, 4>, cudaFuncAttributeMaxDynamicSharedMemorySize, (int)smem_for(32));
    cudaFuncSetAttribute((const void*)layer_kernel<2, 2>, cudaFuncAttributeMaxDynamicSharedMemorySize, (int)smem_for(16));

    float* wdT_dev; float* wrT_dev;
    cudaGetSymbolAddress((void**)&wdT_dev, g_WdT2);
    cudaGetSymbolAddress((void**)&wrT_dev, g_WrT2);

    prep_dup<<<dim3(512, NLAY), 256>>>(Wd, wdT_dev, 512);
    prep_dup<<<dim3(256, NLAY), 256>>>(Wr, wrT_dev, 256);
    start_conv<<<dim3(WIN / 256, Bsz), 256>>>(x, Wst, bst);

    int suf[NLAY + 1];
    suf[NLAY] = 0;
    for (int i = NLAY - 1; i >= 0; i--) suf[i] = suf[i + 1] + DILS[i];

    for (int i = 0; i < NLAY; i++) {
        int N  = 1 + suf[i + 1];
        int u0 = WIN - N;
        int pp = i & 1;
        const float* bdp   = bd + (size_t)i * RES;
        const float* brp   = br + (size_t)i * RES;
        const float* wdt_l = wdT_dev + (size_t)i * 512 * ASROW;
        const float* wrt_l = wrT_dev + (size_t)i * 256 * ASROW;

        int BN = (N > 64 * 37) ? 96 : (N > 32 * 37) ? 64 : (N > 16 * 37) ? 32 : 16;
        int gx = (N + BN - 1) / BN;
        dim3 grid(gx, Bsz);
        size_t sm = smem_for(BN);
        switch (BN) {
            case 96: layer_kernel<8, 3><<<grid, 384, sm>>>(pp, wdt_l, bdp, wrt_l, brp, DILS[i], u0, i); break;
            case 64: layer_kernel<4, 4><<<grid, 512, sm>>>(pp, wdt_l, bdp, wrt_l, brp, DILS[i], u0, i); break;
            case 32: layer_kernel<2, 4><<<grid, 512, sm>>>(pp, wdt_l, bdp, wrt_l, brp, DILS[i], u0, i); break;
            default: layer_kernel<2, 2><<<grid, 256, sm>>>(pp, wdt_l, bdp, wrt_l, brp, DILS[i], u0, i); break;
        }
    }

    skip_kernel<<<dim3(Bsz, SKIPC / 64), 256>>>(Ws, bs);
    end_kernel<<<Bsz, 256>>>(We1, be1, We2, be2, out);
}

// round 9
// speedup vs baseline: 1.9732x; 1.9732x over previous
#include <cuda_runtime.h>
#include <cuda_bf16.h>
#include <cstdint>

#define Tlen  8192
#define Bsz   4
#define RES   256
#define SKIPC 512
#define NCLSC 256
#define NLAY  30
#define WIN   3072
#define HSTR  3200

// ---------------- device scratch (allocation-free) ----------------
__device__ float g_h[2][Bsz][RES][HSTR];                 // ping-pong hidden state; pads zero
__device__ uint32_t g_Ad[(size_t)NLAY * 16 * 2 * 2 * 2048];  // conv A fragments  [lay][c32][s][hi/lo][2048]
__device__ uint32_t g_Ar[(size_t)NLAY * 8  * 2 * 2 * 2048];  // resid A fragments
__device__ float g_gLast[NLAY][Bsz][RES];
__device__ float g_skip[Bsz][SKIPC];

// ---------------- helpers ----------------
__device__ __forceinline__ uint32_t su32(const void* p) {
    return (uint32_t)__cvta_generic_to_shared(p);
}
__device__ __forceinline__ uint32_t pk2b(__nv_bfloat16 a, __nv_bfloat16 b) {
    __nv_bfloat162 v; v.x = a; v.y = b;
    return *(uint32_t*)&v;
}
__device__ __forceinline__ float gate_fn(float d) {
    float e1 = __expf(-d);
    float sg = __fdividef(1.f, 1.f + e1);
    float th = __fdividef(2.f, 1.f + e1 * e1) - 1.f;
    return th * sg;
}
__device__ __forceinline__ void hmma(float* d, const uint32_t* a, uint32_t b0, uint32_t b1) {
    asm volatile(
        "mma.sync.aligned.m16n8k16.row.col.f32.bf16.bf16.f32 "
        "{%0,%1,%2,%3}, {%4,%5,%6,%7}, {%8,%9}, {%0,%1,%2,%3};"
        : "+f"(d[0]), "+f"(d[1]), "+f"(d[2]), "+f"(d[3])
        : "r"(a[0]), "r"(a[1]), "r"(a[2]), "r"(a[3]), "r"(b0), "r"(b1));
}

#define CPA16(d, s) asm volatile("cp.async.cg.shared.global [%0],[%1],16;\n" :: "r"(d), "l"(s))
#define CPCOMMIT()  asm volatile("cp.async.commit_group;\n")
#define CPWAIT0()   asm volatile("cp.async.wait_group 0;\n" ::: "memory")

// ---------------- prep: weights -> bf16 hi/lo, A-fragment order ----------------
// a0=(row g, k 2t), a1=(row g+8, k 2t), a2=(row g, k 2t+8), a3=(row g+8, k 2t+8)
// conv k-order: k = tap*256 + ci  (tap-major)
__global__ void prep_w(const float* __restrict__ W, uint32_t* __restrict__ dst, int conv) {
    int c16 = blockIdx.x, lay = blockIdx.y;
    int tid = threadIdx.x;
    int mt = tid >> 5, L = tid & 31, g = L >> 2, t = L & 3;
    uint32_t hi[4], lo[4];
#pragma unroll
    for (int r = 0; r < 4; r++) {
        int mm = mt * 16 + g + (r & 1) * 8;
        int kb = 2 * t + (r >> 1) * 8;
        float f0, f1;
        if (conv) {
            int tap = c16 >> 4;
            int ci  = (c16 & 15) * 16 + kb;
            const float* p = W + (((size_t)lay * 256 + mm) * 256 + ci) * 2 + tap;
            f0 = p[0]; f1 = p[2];
        } else {
            int k = c16 * 16 + kb;
            const float* p = W + ((size_t)lay * 256 + mm) * 256 + k;
            f0 = p[0]; f1 = p[1];
        }
        __nv_bfloat16 h0 = __float2bfloat16(f0), h1 = __float2bfloat16(f1);
        hi[r] = pk2b(h0, h1);
        lo[r] = pk2b(__float2bfloat16(f0 - __bfloat162float(h0)),
                     __float2bfloat16(f1 - __bfloat162float(h1)));
    }
    int K32 = conv ? 16 : 8;
    int c32 = c16 >> 1, s = c16 & 1;
    size_t base = ((((size_t)lay * K32 + c32) * 2 + s) * 2) * 2048 + (size_t)(mt * 32 + L) * 4;
#pragma unroll
    for (int r = 0; r < 4; r++) { dst[base + r] = hi[r]; dst[base + 2048 + r] = lo[r]; }
}

// ---------------- start conv ----------------
__global__ void start_conv(const float* __restrict__ x, const float* __restrict__ Wst,
                           const float* __restrict__ bst) {
    int b = blockIdx.y;
    int u = blockIdx.x * 256 + threadIdx.x;
    int t = (Tlen - WIN) + u;
    float x0 = x[b * Tlen + t - 1], x1 = x[b * Tlen + t];
    for (int c = 0; c < RES; c++)
        g_h[0][b][c][u] = bst[c] + Wst[2 * c] * x0 + Wst[2 * c + 1] * x1;
}

// ---------------- fused HMMA layer ----------------
// 512 thr = 16 warps: wr=warp>>2 (M 64-slice), wc=warp&3 (N slice of NT ntiles).
// BN = 32*NT. SMEM: A frag dbuf | B frag dbuf | gs (phase-2 B frags).
template <int NT>
__global__ void __launch_bounds__(512, 1)
layer_mma(int pp, int layer, int dil, int u0,
          const uint32_t* __restrict__ Ac, const uint32_t* __restrict__ Ar,
          const float* __restrict__ bd, const float* __restrict__ br) {
    constexpr int NTB = 4 * NT;
    constexpr int BN  = 8 * NTB;
    constexpr int BSOFF = 16384;
    constexpr int GSOFF = 16384 + 512 * NTB;

    extern __shared__ uint32_t sm[];
    const int tid = threadIdx.x, L = tid & 31, w = tid >> 5;
    const int wr = w >> 2, wc = w & 3, g = L >> 2, t = L & 3;
    const int b = blockIdx.y, ub = u0 + blockIdx.x * BN;

    const float* hin  = &g_h[pp][b][0][0];
    float*       hout = &g_h[pp ^ 1][b][0][0];

    float acc[4][NT][4];
#pragma unroll
    for (int mt = 0; mt < 4; mt++)
#pragma unroll
        for (int nl = 0; nl < NT; nl++)
#pragma unroll
            for (int e = 0; e < 4; e++) acc[mt][nl][e] = 0.f;

    auto stageA = [&](int buf, const uint32_t* src) {   // 8192 u32 contiguous
        uint32_t* dstb = sm + buf * 8192;
        for (int i = tid; i < 2048; i += 512)
            CPA16(su32(dstb + 4 * i), src + 4 * i);
    };
    auto stageB = [&](int buf, int c) {                 // conv chunk c: convert+split into B frags
        int tap = c >> 3;
        int off = tap ? 0 : dil;
        int cibase = (c * 32) & 255;
#pragma unroll
        for (int e = tid; e < 128 * NTB; e += 512) {
            int LL = e & 31, x = e >> 5;
            int nt = x % NTB, y = x / NTB;
            int r = y & 1, s = y >> 1;
            int gg = LL >> 2, tt = LL & 3;
            int kk = 2 * tt + r * 8;
            int ci = cibase + s * 16 + kk;
            const float* p = hin + (size_t)ci * HSTR + (ub + nt * 8 + gg - off);
            float f0 = p[0], f1 = p[HSTR];
            __nv_bfloat16 h0 = __float2bfloat16(f0), h1 = __float2bfloat16(f1);
            sm[BSOFF + (((((buf * 2 + s) * 2 + 0) * NTB + nt) * 32 + LL) * 2 + r)] = pk2b(h0, h1);
            sm[BSOFF + (((((buf * 2 + s) * 2 + 1) * NTB + nt) * 32 + LL) * 2 + r)] =
                pk2b(__float2bfloat16(f0 - __bfloat162float(h0)),
                     __float2bfloat16(f1 - __bfloat162float(h1)));
        }
    };

    // compute one k32 chunk; phase=0: B from staged buf, phase=1: B from gs at ktile base kt0
    auto compute = [&](int buf, int phase, int kt0) {
#pragma unroll
        for (int s = 0; s < 2; s++) {
            uint4 ah[4], al[4];
            const uint32_t* Abase = sm + (buf * 2 + s) * 2 * 2048;
#pragma unroll
            for (int mt = 0; mt < 4; mt++) {
                int gmt = wr * 4 + mt;
                ah[mt] = *(const uint4*)(Abase + (gmt * 32 + L) * 4);
                al[mt] = *(const uint4*)(Abase + 2048 + (gmt * 32 + L) * 4);
            }
#pragma unroll
            for (int nl = 0; nl < NT; nl++) {
                int nt = wc * NT + nl;
                uint32_t bh0, bh1, bl0, bl1;
                if (phase == 0) {
                    int ih = BSOFF + (((((buf * 2 + s) * 2 + 0) * NTB + nt) * 32 + L) * 2);
                    int il = BSOFF + (((((buf * 2 + s) * 2 + 1) * NTB + nt) * 32 + L) * 2);
                    bh0 = sm[ih]; bh1 = sm[ih + 1];
                    bl0 = sm[il]; bl1 = sm[il + 1];
                } else {
                    int kt = kt0 + s;
                    int ih = GSOFF + ((((kt * 2 + 0) * NTB + nt) * 32 + L) * 2);
                    int il = GSOFF + ((((kt * 2 + 1) * NTB + nt) * 32 + L) * 2);
                    bh0 = sm[ih]; bh1 = sm[ih + 1];
                    bl0 = sm[il]; bl1 = sm[il + 1];
                }
#pragma unroll
                for (int mt = 0; mt < 4; mt++) {
                    hmma(acc[mt][nl], (const uint32_t*)&ah[mt], bh0, bh1);
                    hmma(acc[mt][nl], (const uint32_t*)&al[mt], bh0, bh1);
                    hmma(acc[mt][nl], (const uint32_t*)&ah[mt], bl0, bl1);
                }
            }
        }
    };

    // ---- phase 1: conv GEMM, 16 k32 chunks ----
    stageA(0, Ac); CPCOMMIT();
    stageB(0, 0);
    int buf = 0;
    for (int c = 0; c < 16; c++) {
        CPWAIT0(); __syncthreads();
        if (c + 1 < 16) { stageA(buf ^ 1, Ac + (size_t)(c + 1) * 8192); stageB(buf ^ 1, c + 1); }
        else            { stageA(buf ^ 1, Ar); }   // prefetch phase-2 chunk 0
        CPCOMMIT();
        compute(buf, 0, 0);
        buf ^= 1;
    }

    // ---- gate: acc -> gs (phase-2 B fragments, bf16 hi/lo) ----
#pragma unroll
    for (int mt = 0; mt < 4; mt++)
#pragma unroll
        for (int nl = 0; nl < NT; nl++)
#pragma unroll
            for (int e = 0; e < 4; e++) {
                int mm = wr * 64 + mt * 16 + g + (e >> 1) * 8;
                int n  = wc * NT * 8 + nl * 8 + 2 * t + (e & 1);
                float gv = gate_fn(acc[mt][nl][e] + bd[mm]);
                if (ub + n == WIN - 1) g_gLast[layer][b][mm] = gv;
                __nv_bfloat16 hh = __float2bfloat16(gv);
                __nv_bfloat16 ll = __float2bfloat16(gv - __bfloat162float(hh));
                int kt2 = mm >> 4, kk2 = mm & 15;
                int r2 = kk2 >> 3, t2 = (kk2 & 7) >> 1, hp = kk2 & 1;
                int L2 = (n & 7) * 4 + t2;
                int nt2 = n >> 3;
                int ih = GSOFF + ((((kt2 * 2 + 0) * NTB + nt2) * 32 + L2) * 2 + r2);
                int il = GSOFF + ((((kt2 * 2 + 1) * NTB + nt2) * 32 + L2) * 2 + r2);
                ((__nv_bfloat16*)&sm[ih])[hp] = hh;
                ((__nv_bfloat16*)&sm[il])[hp] = ll;
                acc[mt][nl][e] = 0.f;
            }

    // ---- phase 2: residual GEMM, 8 k32 chunks, B = gs ----
    for (int c = 0; c < 8; c++) {
        CPWAIT0(); __syncthreads();      // also publishes gs before first read
        if (c + 1 < 8) stageA(buf ^ 1, Ar + (size_t)(c + 1) * 8192);
        CPCOMMIT();
        compute(buf, 1, c * 2);
        buf ^= 1;
    }

    // ---- residual epilogue ----
#pragma unroll
    for (int mt = 0; mt < 4; mt++)
#pragma unroll
        for (int nl = 0; nl < NT; nl++)
#pragma unroll
            for (int e = 0; e < 4; e++) {
                int mm = wr * 64 + mt * 16 + g + (e >> 1) * 8;
                int n  = wc * NT * 8 + nl * 8 + 2 * t + (e & 1);
                int uu = ub + n;
                if (uu < WIN)
                    hout[(size_t)mm * HSTR + uu] =
                        hin[(size_t)mm * HSTR + uu] + acc[mt][nl][e] + br[mm];
            }
}

// ---------------- skip head ----------------
__global__ void skip_kernel(const float* __restrict__ Ws, const float* __restrict__ bs) {
    int b = blockIdx.x;
    int w = threadIdx.x >> 5, lane = threadIdx.x & 31;
    int so_base = blockIdx.y * 64 + w * 8;
    for (int oi = 0; oi < 8; oi++) {
        int so = so_base + oi;
        float v = (lane < NLAY) ? bs[lane * SKIPC + so] : 0.f;
        for (int l = 0; l < NLAY; l++) {
            const float* wr = Ws + ((size_t)l * SKIPC + so) * RES;
            const float* gg = &g_gLast[l][b][0];
#pragma unroll
            for (int k = lane; k < RES; k += 32) v += wr[k] * gg[k];
        }
#pragma unroll
        for (int s = 16; s; s >>= 1) v += __shfl_xor_sync(0xffffffffu, v, s);
        if (lane == 0) g_skip[b][so] = fmaxf(v, 0.f);
    }
}

// ---------------- end head ----------------
__global__ void end_kernel(const float* __restrict__ We1, const float* __restrict__ be1,
                           const float* __restrict__ We2, const float* __restrict__ be2,
                           float* __restrict__ out) {
    __shared__ float sk[SKIPC];
    __shared__ float mid[SKIPC];
    int b = blockIdx.x, tid = threadIdx.x;
    int w = tid >> 5, lane = tid & 31;
    for (int i = tid; i < SKIPC; i += 256) sk[i] = g_skip[b][i];
    __syncthreads();
    for (int oi = 0; oi < 64; oi++) {
        int so = w * 64 + oi;
        const float* row = We1 + (size_t)so * SKIPC;
        float v = 0.f;
#pragma unroll
        for (int k = lane; k < SKIPC; k += 32) v += row[k] * sk[k];
#pragma unroll
        for (int s = 16; s; s >>= 1) v += __shfl_xor_sync(0xffffffffu, v, s);
        if (lane == 0) mid[so] = fmaxf(v + be1[so], 0.f);
    }
    __syncthreads();
    for (int oi = 0; oi < 32; oi++) {
        int nc = w * 32 + oi;
        const float* row = We2 + (size_t)nc * SKIPC;
        float v = 0.f;
#pragma unroll
        for (int k = lane; k < SKIPC; k += 32) v += row[k] * mid[k];
#pragma unroll
        for (int s = 16; s; s >>= 1) v += __shfl_xor_sync(0xffffffffu, v, s);
        if (lane == 0) out[b * NCLSC + nc] = v + be2[nc];
    }
}

// ---------------- host ----------------
static const int DILS[NLAY] = {1,2,4,8,16,32,64,128,256,512,
                               1,2,4,8,16,32,64,128,256,512,
                               1,2,4,8,16,32,64,128,256,512};

static inline size_t smem_for(int NT) {
    return (size_t)(16384 + 2560 * 4 * NT) * 4;
}

extern "C" void kernel_launch(void* const* d_in, const int* in_sizes, int n_in,
                              void* d_out, int out_size) {
    (void)in_sizes; (void)n_in; (void)out_size;
    const float* x   = (const float*)d_in[0];
    const float* Wst = (const float*)d_in[1];
    const float* bst = (const float*)d_in[2];
    const float* Wd  = (const float*)d_in[3];
    const float* bd  = (const float*)d_in[4];
    const float* Wr  = (const float*)d_in[5];
    const float* br  = (const float*)d_in[6];
    const float* Ws  = (const float*)d_in[7];
    const float* bs  = (const float*)d_in[8];
    const float* We1 = (const float*)d_in[9];
    const float* be1 = (const float*)d_in[10];
    const float* We2 = (const float*)d_in[11];
    const float* be2 = (const float*)d_in[12];
    float* out = (float*)d_out;

    cudaFuncSetAttribute((const void*)layer_mma<3>, cudaFuncAttributeMaxDynamicSharedMemorySize, (int)smem_for(3));
    cudaFuncSetAttribute((const void*)layer_mma<2>, cudaFuncAttributeMaxDynamicSharedMemorySize, (int)smem_for(2));
    cudaFuncSetAttribute((const void*)layer_mma<1>, cudaFuncAttributeMaxDynamicSharedMemorySize, (int)smem_for(1));

    uint32_t *ad_dev, *ar_dev;
    cudaGetSymbolAddress((void**)&ad_dev, g_Ad);
    cudaGetSymbolAddress((void**)&ar_dev, g_Ar);

    prep_w<<<dim3(32, NLAY), 512>>>(Wd, ad_dev, 1);
    prep_w<<<dim3(16, NLAY), 512>>>(Wr, ar_dev, 0);
    start_conv<<<dim3(WIN / 256, Bsz), 256>>>(x, Wst, bst);

    int suf[NLAY + 1];
    suf[NLAY] = 0;
    for (int i = NLAY - 1; i >= 0; i--) suf[i] = suf[i + 1] + DILS[i];

    for (int i = 0; i < NLAY; i++) {
        int N  = 1 + suf[i + 1];
        int u0 = WIN - N;
        int pp = i & 1;
        const uint32_t* ac = ad_dev + (size_t)i * 16 * 8192;
        const uint32_t* ar = ar_dev + (size_t)i * 8 * 8192;
        const float* bdp = bd + (size_t)i * RES;
        const float* brp = br + (size_t)i * RES;

        int NT = (N > 2368) ? 3 : (N > 1184) ? 2 : 1;
        int BN = 32 * NT;
        int gx = (N + BN - 1) / BN;
        dim3 grid(gx, Bsz);
        switch (NT) {
            case 3: layer_mma<3><<<grid, 512, smem_for(3)>>>(pp, i, DILS[i], u0, ac, ar, bdp, brp); break;
            case 2: layer_mma<2><<<grid, 512, smem_for(2)>>>(pp, i, DILS[i], u0, ac, ar, bdp, brp); break;
            default: layer_mma<1><<<grid, 512, smem_for(1)>>>(pp, i, DILS[i], u0, ac, ar, bdp, brp); break;
        }
    }

    skip_kernel<<<dim3(Bsz, SKIPC / 64), 256>>>(Ws, bs);
    end_kernel<<<Bsz, 256>>>(We1, be1, We2, be2, out);
}